// round 5
// baseline (speedup 1.0000x reference)
#include <cuda_runtime.h>
#include <cuda_bf16.h>
#include <math.h>

#define TILE_M 256
#define THREADS 512
#define SAB 136   // bf16 elements per smem row (272B) -> conflict-free LDSM

#define MAX_N 100096
#define W1_OFF 0
#define W2_OFF (256*128)
#define W3_OFF (256*128 + 128*128)
#define W_TOTAL (256*128 + 2*128*128)

// smem: sA[256*SAB bf16] | sB[128*SAB bf16] | sIdx[512 int] | sW4[128 float]
#define SMEM_BYTES ((TILE_M + 128)*SAB*2 + 512*4 + 128*4)

__device__ __nv_bfloat16 g_xbf[(size_t)MAX_N * 128];
__device__ __nv_bfloat16 g_wbf[W_TOTAL];

// ---------------- prep: fp32 -> bf16 ----------------
__global__ void cvt_x_kernel(const float* __restrict__ x, int n4) {
    int i = blockIdx.x * blockDim.x + threadIdx.x;   // over N*32 float4s
    if (i >= n4) return;
    float4 v = ((const float4*)x)[i];
    __nv_bfloat162 p0 = __floats2bfloat162_rn(v.x, v.y);
    __nv_bfloat162 p1 = __floats2bfloat162_rn(v.z, v.w);
    uint2 o; o.x = *(unsigned*)&p0; o.y = *(unsigned*)&p1;
    ((uint2*)g_xbf)[i] = o;
}
__global__ void cvt_w_kernel(const float* __restrict__ W1,
                             const float* __restrict__ W2,
                             const float* __restrict__ W3) {
    int i = blockIdx.x * blockDim.x + threadIdx.x;   // over W_TOTAL/4 float4s
    if (i >= W_TOTAL / 4) return;
    int e = i * 4;
    const float* src = (e < W2_OFF) ? (W1 + e)
                     : (e < W3_OFF) ? (W2 + (e - W2_OFF))
                                    : (W3 + (e - W3_OFF));
    float4 v = *(const float4*)src;
    __nv_bfloat162 p0 = __floats2bfloat162_rn(v.x, v.y);
    __nv_bfloat162 p1 = __floats2bfloat162_rn(v.z, v.w);
    uint2 o; o.x = *(unsigned*)&p0; o.y = *(unsigned*)&p1;
    ((uint2*)g_wbf)[i] = o;
}

// ---------------- mma helpers ----------------
__device__ __forceinline__ void ldsm_x4(unsigned* r, unsigned addr) {
    asm volatile("ldmatrix.sync.aligned.m8n8.x4.shared.b16 {%0,%1,%2,%3}, [%4];"
        : "=r"(r[0]), "=r"(r[1]), "=r"(r[2]), "=r"(r[3]) : "r"(addr));
}
__device__ __forceinline__ void ldsm_x4_t(unsigned* r, unsigned addr) {
    asm volatile("ldmatrix.sync.aligned.m8n8.x4.trans.shared.b16 {%0,%1,%2,%3}, [%4];"
        : "=r"(r[0]), "=r"(r[1]), "=r"(r[2]), "=r"(r[3]) : "r"(addr));
}
__device__ __forceinline__ void mma_bf16(float* c, const unsigned* a, const unsigned* b) {
    asm volatile(
        "mma.sync.aligned.m16n8k16.row.col.f32.bf16.bf16.f32 "
        "{%0,%1,%2,%3},{%4,%5,%6,%7},{%8,%9},{%0,%1,%2,%3};"
        : "+f"(c[0]), "+f"(c[1]), "+f"(c[2]), "+f"(c[3])
        : "r"(a[0]), "r"(a[1]), "r"(a[2]), "r"(a[3]), "r"(b[0]), "r"(b[1]));
}

__global__ void __launch_bounds__(THREADS, 1)
edgepred_bf16_kernel(
    const int* __restrict__ ei,
    const float* __restrict__ b1, const float* __restrict__ b2,
    const float* __restrict__ b3,
    const float* __restrict__ W4, const float* __restrict__ b4,
    float* __restrict__ out, int E, int N)
{
    extern __shared__ char smem_raw[];
    __nv_bfloat16* sA = (__nv_bfloat16*)smem_raw;            // 256 x SAB
    __nv_bfloat16* sB = sA + TILE_M * SAB;                   // 128 x SAB
    int*   sIdx = (int*)(sB + 128 * SAB);                    // 512
    float* sW4  = (float*)(sIdx + 512);                      // 128

    const int tid    = threadIdx.x;
    const int lane   = tid & 31;
    const int wid    = tid >> 5;                 // 0..15
    const int warp_m = wid >> 2;                 // 0..3 -> rows [warp_m*64, +64)
    const int warp_n = wid & 3;                  // 0..3 -> cols [warp_n*32, +32)
    const int qid    = lane >> 2;
    const int tig    = lane & 3;
    const long long tile0 = (long long)blockIdx.x * TILE_M;

    const unsigned sA_u = (unsigned)__cvta_generic_to_shared(sA);
    const unsigned sB_u = (unsigned)__cvta_generic_to_shared(sB);

    // ---- edge indices (src 0..255 / dst 256..511), clamped ----
    {
        int half = (tid < 256) ? 0 : 1;
        int r    = tid & 255;
        long long e = tile0 + r;
        int idx = 0;
        if (e < E) idx = ei[(long long)half * E + e];
        if (idx < 0)  idx = 0;
        if (idx >= N) idx = N - 1;
        sIdx[half * 256 + r] = idx;
    }
    __syncthreads();

    // ---- coalesced bf16 row loaders: one warp per 256B row ----
    auto copy_row = [&](const __nv_bfloat16* srcRow, __nv_bfloat16* dstRow) {
        uint2 v = ((const uint2*)srcRow)[lane];          // 8B per lane = full row
        *(uint2*)(dstRow + lane * 4) = v;                // STS.64 conflict-free
    };
    auto load_act = [&](const int* idxs) {
        #pragma unroll
        for (int r = 0; r < 16; ++r) {
            int row = wid + r * 16;
            int node = idxs[row];
            copy_row(g_xbf + (size_t)node * 128, sA + row * SAB);
        }
    };
    auto load_w = [&](const __nv_bfloat16* W) {
        #pragma unroll
        for (int r = 0; r < 8; ++r) {
            int row = wid + r * 16;
            copy_row(W + row * 128, sB + row * SAB);
        }
    };

    // ---- per-lane LDSM base addresses ----
    const int sub = lane >> 3;
    const int r8  = lane & 7;
    const unsigned aBase = sA_u + (((sub & 1) * 8 + r8) * SAB + (sub >> 1) * 8) * 2;
    const unsigned bBase = sB_u + (((sub & 1) * 8 + r8) * SAB + warp_n * 32 + (sub >> 1) * 8) * 2;

    float acc[4][4][4];
    auto zero_acc = [&]() {
        #pragma unroll
        for (int mt = 0; mt < 4; ++mt)
            #pragma unroll
            for (int nt = 0; nt < 4; ++nt)
                #pragma unroll
                for (int i = 0; i < 4; ++i) acc[mt][nt][i] = 0.f;
    };

    // 256x128x128 GEMM pass (per warp: 64x32): sA @ sB -> acc
    auto run_mma = [&]() {
        #pragma unroll
        for (int kt = 0; kt < 8; ++kt) {
            unsigned a[4][4], b[2][4];
            #pragma unroll
            for (int mt = 0; mt < 4; ++mt)
                ldsm_x4(a[mt], aBase + (unsigned)((warp_m * 64 + mt * 16) * SAB + kt * 16) * 2);
            #pragma unroll
            for (int ntp = 0; ntp < 2; ++ntp)
                ldsm_x4_t(b[ntp], bBase + (unsigned)(kt * 16 * SAB + ntp * 16) * 2);
            #pragma unroll
            for (int mt = 0; mt < 4; ++mt)
                #pragma unroll
                for (int nt = 0; nt < 4; ++nt)
                    mma_bf16(acc[mt][nt], a[mt], &b[nt >> 1][(nt & 1) * 2]);
        }
    };

    // bias + relu -> bf16 back into sA
    auto epilogue = [&](const float* __restrict__ bias) {
        #pragma unroll
        for (int mt = 0; mt < 4; ++mt) {
            int row = warp_m * 64 + mt * 16 + qid;
            #pragma unroll
            for (int nt = 0; nt < 4; ++nt) {
                int col = warp_n * 32 + nt * 8 + 2 * tig;
                float bb0 = __ldg(&bias[col]);
                float bb1 = __ldg(&bias[col + 1]);
                float v0 = fmaxf(acc[mt][nt][0] + bb0, 0.f);
                float v1 = fmaxf(acc[mt][nt][1] + bb1, 0.f);
                float v2 = fmaxf(acc[mt][nt][2] + bb0, 0.f);
                float v3 = fmaxf(acc[mt][nt][3] + bb1, 0.f);
                *(__nv_bfloat162*)(sA + row * SAB + col)       = __floats2bfloat162_rn(v0, v1);
                *(__nv_bfloat162*)(sA + (row + 8) * SAB + col) = __floats2bfloat162_rn(v2, v3);
            }
        }
    };

    // ======== Layer 1, pass A: x_i @ W1[0:128] ========
    load_act(sIdx);
    load_w(g_wbf + W1_OFF);
    __syncthreads();
    zero_acc();
    run_mma();
    __syncthreads();

    // ======== Layer 1, pass B: + x_j @ W1[128:256] ========
    load_act(sIdx + 256);
    load_w(g_wbf + W1_OFF + 128 * 128);
    __syncthreads();
    run_mma();
    __syncthreads();
    load_w(g_wbf + W2_OFF);   // LDGs first -> overlap with epilogue math
    epilogue(b1);
    __syncthreads();

    // ======== Layer 2 ========
    zero_acc();
    run_mma();
    __syncthreads();
    load_w(g_wbf + W3_OFF);
    epilogue(b2);
    __syncthreads();

    // ======== Layer 3 ========
    zero_acc();
    run_mma();
    __syncthreads();
    if (tid < 128) sW4[tid] = W4[tid];
    epilogue(b3);
    __syncthreads();

    // ======== Layer 4: dot(h3, W4) + sigmoid ========
    if (tid < 256) {
        long long e = tile0 + tid;
        if (e < E) {
            float z = __ldg(b4);
            const __nv_bfloat162* hr = (const __nv_bfloat162*)(sA + tid * SAB);
            #pragma unroll
            for (int j = 0; j < 64; ++j) {
                float2 h2 = __bfloat1622float2(hr[j]);
                z += h2.x * sW4[2 * j] + h2.y * sW4[2 * j + 1];
            }
            out[e] = 1.f / (1.f + expf(-z));
        }
    }
}

extern "C" void kernel_launch(void* const* d_in, const int* in_sizes, int n_in,
                              void* d_out, int out_size)
{
    const float* x  = (const float*)d_in[0];
    const int*   ei = (const int*)d_in[1];
    const float* W1 = (const float*)d_in[2];
    const float* b1 = (const float*)d_in[3];
    const float* W2 = (const float*)d_in[4];
    const float* b2 = (const float*)d_in[5];
    const float* W3 = (const float*)d_in[6];
    const float* b3 = (const float*)d_in[7];
    const float* W4 = (const float*)d_in[8];
    const float* b4 = (const float*)d_in[9];
    float* out = (float*)d_out;

    int E = in_sizes[1] / 2;    // edge_index is (2, E)
    int N = in_sizes[0] / 128;  // x is (N, 128)
    if (N > MAX_N) N = MAX_N;

    // prep: convert x and weights to bf16 scratch
    int n4 = N * 32;
    cvt_x_kernel<<<(n4 + 511) / 512, 512>>>(x, n4);
    cvt_w_kernel<<<(W_TOTAL / 4 + 255) / 256, 256>>>(W1, W2, W3);

    int nTiles = (E + TILE_M - 1) / TILE_M;
    cudaFuncSetAttribute(edgepred_bf16_kernel,
                         cudaFuncAttributeMaxDynamicSharedMemorySize, SMEM_BYTES);
    edgepred_bf16_kernel<<<nTiles, THREADS, SMEM_BYTES>>>(
        ei, b1, b2, b3, W4, b4, out, E, N);
}

// round 6
// speedup vs baseline: 1.1513x; 1.1513x over previous
#include <cuda_runtime.h>
#include <cuda_bf16.h>
#include <math.h>

#define TILE_M 128
#define THREADS 256
#define SAB 136   // bf16 elements per smem row (272B) -> conflict-free LDSM

#define MAX_N 100096
#define W1_OFF 0
#define W2_OFF (256*128)
#define W3_OFF (256*128 + 128*128)
#define W_TOTAL (256*128 + 2*128*128)

// smem: sA[128*SAB bf16] | sB[128*SAB bf16] | sIdx[256 int] | sW4[128 float]
#define SMEM_BYTES (2*128*SAB*2 + 256*4 + 128*4)

__device__ __nv_bfloat16 g_xbf[(size_t)MAX_N * 128];
__device__ __nv_bfloat16 g_wbf[W_TOTAL];

// ---------------- prep: fp32 -> bf16 ----------------
__global__ void cvt_x_kernel(const float* __restrict__ x, int n4) {
    int i = blockIdx.x * blockDim.x + threadIdx.x;   // over N*32 float4s
    if (i >= n4) return;
    float4 v = ((const float4*)x)[i];
    __nv_bfloat162 p0 = __floats2bfloat162_rn(v.x, v.y);
    __nv_bfloat162 p1 = __floats2bfloat162_rn(v.z, v.w);
    uint2 o; o.x = *(unsigned*)&p0; o.y = *(unsigned*)&p1;
    ((uint2*)g_xbf)[i] = o;
}
__global__ void cvt_w_kernel(const float* __restrict__ W1,
                             const float* __restrict__ W2,
                             const float* __restrict__ W3) {
    int i = blockIdx.x * blockDim.x + threadIdx.x;   // over W_TOTAL/4 float4s
    if (i >= W_TOTAL / 4) return;
    int e = i * 4;
    const float* src = (e < W2_OFF) ? (W1 + e)
                     : (e < W3_OFF) ? (W2 + (e - W2_OFF))
                                    : (W3 + (e - W3_OFF));
    float4 v = *(const float4*)src;
    __nv_bfloat162 p0 = __floats2bfloat162_rn(v.x, v.y);
    __nv_bfloat162 p1 = __floats2bfloat162_rn(v.z, v.w);
    uint2 o; o.x = *(unsigned*)&p0; o.y = *(unsigned*)&p1;
    ((uint2*)g_wbf)[i] = o;
}

// ---------------- mma helpers ----------------
__device__ __forceinline__ void ldsm_x4(unsigned* r, unsigned addr) {
    asm volatile("ldmatrix.sync.aligned.m8n8.x4.shared.b16 {%0,%1,%2,%3}, [%4];"
        : "=r"(r[0]), "=r"(r[1]), "=r"(r[2]), "=r"(r[3]) : "r"(addr));
}
__device__ __forceinline__ void ldsm_x4_t(unsigned* r, unsigned addr) {
    asm volatile("ldmatrix.sync.aligned.m8n8.x4.trans.shared.b16 {%0,%1,%2,%3}, [%4];"
        : "=r"(r[0]), "=r"(r[1]), "=r"(r[2]), "=r"(r[3]) : "r"(addr));
}
__device__ __forceinline__ void mma_bf16(float* c, const unsigned* a, const unsigned* b) {
    asm volatile(
        "mma.sync.aligned.m16n8k16.row.col.f32.bf16.bf16.f32 "
        "{%0,%1,%2,%3},{%4,%5,%6,%7},{%8,%9},{%0,%1,%2,%3};"
        : "+f"(c[0]), "+f"(c[1]), "+f"(c[2]), "+f"(c[3])
        : "r"(a[0]), "r"(a[1]), "r"(a[2]), "r"(a[3]), "r"(b[0]), "r"(b[1]));
}

__global__ void __launch_bounds__(THREADS, 2)
edgepred_bf16_kernel(
    const int* __restrict__ ei,
    const float* __restrict__ b1, const float* __restrict__ b2,
    const float* __restrict__ b3,
    const float* __restrict__ W4, const float* __restrict__ b4,
    float* __restrict__ out, int E, int N)
{
    extern __shared__ char smem_raw[];
    __nv_bfloat16* sA = (__nv_bfloat16*)smem_raw;            // 128 x SAB
    __nv_bfloat16* sB = sA + 128 * SAB;                      // 128 x SAB
    int*   sIdx = (int*)(sB + 128 * SAB);                    // 256
    float* sW4  = (float*)(sIdx + 256);                      // 128

    const int tid    = threadIdx.x;
    const int lane   = tid & 31;
    const int wid    = tid >> 5;                 // 0..7
    const int warp_m = wid >> 2;                 // 0..1 -> rows [warp_m*64, +64)
    const int warp_n = wid & 3;                  // 0..3 -> cols [warp_n*32, +32)
    const int qid    = lane >> 2;
    const int tig    = lane & 3;
    const long long tile0 = (long long)blockIdx.x * TILE_M;

    const unsigned sA_u = (unsigned)__cvta_generic_to_shared(sA);
    const unsigned sB_u = (unsigned)__cvta_generic_to_shared(sB);

    // ---- edge indices (src / dst), clamped ----
    {
        int half = (tid < 128) ? 0 : 1;
        int r    = tid & 127;
        long long e = tile0 + r;
        int idx = 0;
        if (e < E) idx = ei[(long long)half * E + e];
        if (idx < 0)  idx = 0;
        if (idx >= N) idx = N - 1;
        sIdx[half * 128 + r] = idx;
    }
    __syncthreads();

    // ---- coalesced bf16 row loaders: one warp per 256B row ----
    auto copy_row = [&](const __nv_bfloat16* srcRow, __nv_bfloat16* dstRow) {
        uint2 v = ((const uint2*)srcRow)[lane];          // 8B/lane = full 256B row
        *(uint2*)(dstRow + lane * 4) = v;                // STS.64 conflict-free
    };
    auto load_act = [&](const int* idxs) {
        #pragma unroll
        for (int r = 0; r < 16; ++r) {
            int row = wid + r * 8;
            int node = idxs[row];
            copy_row(g_xbf + (size_t)node * 128, sA + row * SAB);
        }
    };
    auto load_w = [&](const __nv_bfloat16* W) {
        #pragma unroll
        for (int r = 0; r < 16; ++r) {
            int row = wid + r * 8;
            copy_row(W + row * 128, sB + row * SAB);
        }
    };

    // ---- per-lane LDSM base addresses ----
    const int sub = lane >> 3;
    const int r8  = lane & 7;
    const unsigned aBase = sA_u + (((sub & 1) * 8 + r8) * SAB + (sub >> 1) * 8) * 2;
    const unsigned bBase = sB_u + (((sub & 1) * 8 + r8) * SAB + warp_n * 32 + (sub >> 1) * 8) * 2;

    float acc[4][4][4];
    auto zero_acc = [&]() {
        #pragma unroll
        for (int mt = 0; mt < 4; ++mt)
            #pragma unroll
            for (int nt = 0; nt < 4; ++nt)
                #pragma unroll
                for (int i = 0; i < 4; ++i) acc[mt][nt][i] = 0.f;
    };

    // 128x128x128 GEMM pass (per warp: 64x32): sA @ sB -> acc
    auto run_mma = [&]() {
        #pragma unroll
        for (int kt = 0; kt < 8; ++kt) {
            unsigned a[4][4], b[2][4];
            #pragma unroll
            for (int mt = 0; mt < 4; ++mt)
                ldsm_x4(a[mt], aBase + (unsigned)((warp_m * 64 + mt * 16) * SAB + kt * 16) * 2);
            #pragma unroll
            for (int ntp = 0; ntp < 2; ++ntp)
                ldsm_x4_t(b[ntp], bBase + (unsigned)(kt * 16 * SAB + ntp * 16) * 2);
            #pragma unroll
            for (int mt = 0; mt < 4; ++mt)
                #pragma unroll
                for (int nt = 0; nt < 4; ++nt)
                    mma_bf16(acc[mt][nt], a[mt], &b[nt >> 1][(nt & 1) * 2]);
        }
    };

    // bias + relu -> bf16 back into sA
    auto epilogue = [&](const float* __restrict__ bias) {
        #pragma unroll
        for (int mt = 0; mt < 4; ++mt) {
            int row = warp_m * 64 + mt * 16 + qid;
            #pragma unroll
            for (int nt = 0; nt < 4; ++nt) {
                int col = warp_n * 32 + nt * 8 + 2 * tig;
                float bb0 = __ldg(&bias[col]);
                float bb1 = __ldg(&bias[col + 1]);
                float v0 = fmaxf(acc[mt][nt][0] + bb0, 0.f);
                float v1 = fmaxf(acc[mt][nt][1] + bb1, 0.f);
                float v2 = fmaxf(acc[mt][nt][2] + bb0, 0.f);
                float v3 = fmaxf(acc[mt][nt][3] + bb1, 0.f);
                *(__nv_bfloat162*)(sA + row * SAB + col)       = __floats2bfloat162_rn(v0, v1);
                *(__nv_bfloat162*)(sA + (row + 8) * SAB + col) = __floats2bfloat162_rn(v2, v3);
            }
        }
    };

    // ======== Layer 1, pass A: x_i @ W1[0:128] ========
    load_act(sIdx);
    load_w(g_wbf + W1_OFF);
    __syncthreads();
    zero_acc();
    run_mma();
    __syncthreads();

    // ======== Layer 1, pass B: + x_j @ W1[128:256] ========
    load_act(sIdx + 128);
    load_w(g_wbf + W1_OFF + 128 * 128);
    __syncthreads();
    run_mma();
    __syncthreads();
    load_w(g_wbf + W2_OFF);   // LDGs first -> overlap with epilogue math
    epilogue(b1);
    __syncthreads();

    // ======== Layer 2 ========
    zero_acc();
    run_mma();
    __syncthreads();
    load_w(g_wbf + W3_OFF);
    epilogue(b2);
    __syncthreads();

    // ======== Layer 3 ========
    zero_acc();
    run_mma();
    __syncthreads();
    if (tid < 128) sW4[tid] = W4[tid];
    epilogue(b3);
    __syncthreads();

    // ======== Layer 4: dot(h3, W4) + sigmoid ========
    if (tid < 128) {
        long long e = tile0 + tid;
        if (e < E) {
            float z = __ldg(b4);
            const __nv_bfloat162* hr = (const __nv_bfloat162*)(sA + tid * SAB);
            #pragma unroll
            for (int j = 0; j < 64; ++j) {
                float2 h2 = __bfloat1622float2(hr[j]);
                z += h2.x * sW4[2 * j] + h2.y * sW4[2 * j + 1];
            }
            out[e] = 1.f / (1.f + expf(-z));
        }
    }
}

extern "C" void kernel_launch(void* const* d_in, const int* in_sizes, int n_in,
                              void* d_out, int out_size)
{
    const float* x  = (const float*)d_in[0];
    const int*   ei = (const int*)d_in[1];
    const float* W1 = (const float*)d_in[2];
    const float* b1 = (const float*)d_in[3];
    const float* W2 = (const float*)d_in[4];
    const float* b2 = (const float*)d_in[5];
    const float* W3 = (const float*)d_in[6];
    const float* b3 = (const float*)d_in[7];
    const float* W4 = (const float*)d_in[8];
    const float* b4 = (const float*)d_in[9];
    float* out = (float*)d_out;

    int E = in_sizes[1] / 2;    // edge_index is (2, E)
    int N = in_sizes[0] / 128;  // x is (N, 128)
    if (N > MAX_N) N = MAX_N;

    // prep: convert x and weights to bf16 scratch
    int n4 = N * 32;
    cvt_x_kernel<<<(n4 + 511) / 512, 512>>>(x, n4);
    cvt_w_kernel<<<(W_TOTAL / 4 + 255) / 256, 256>>>(W1, W2, W3);

    int nTiles = (E + TILE_M - 1) / TILE_M;
    cudaFuncSetAttribute(edgepred_bf16_kernel,
                         cudaFuncAttributeMaxDynamicSharedMemorySize, SMEM_BYTES);
    edgepred_bf16_kernel<<<nTiles, THREADS, SMEM_BYTES>>>(
        ei, b1, b2, b3, W4, b4, out, E, N);
}